// round 1
// baseline (speedup 1.0000x reference)
#include <cuda_runtime.h>

// Batched active-set (water-filling) projection.
// Per row: project y onto {0 <= z <= upper, sum z = 512} replicating the
// reference's fixed-point iteration:
//   phase 0: repeatedly clamp z<0 violators to 0
//   phase 1: repeatedly clamp z>upper violators to upper
//   z = y + (C - s)/n_un over the unclamped set
// C, s, n_un are maintained incrementally (exact same values as the
// reference's masked recomputation, modulo fp reduction order).

#define NCOLS 1024
#define THREADS 256   // 4 elements per thread, float4 loads

__global__ __launch_bounds__(THREADS)
void proj_kernel(const float* __restrict__ y,
                 const float* __restrict__ upper,
                 float* __restrict__ out) {
    const int row = blockIdx.x;
    const int t   = threadIdx.x;

    const float4 yv = reinterpret_cast<const float4*>(y + (size_t)row * NCOLS)[t];
    const float4 uv = reinterpret_cast<const float4*>(upper)[t];

    float yy[4] = {yv.x, yv.y, yv.z, yv.w};
    float uu[4] = {uv.x, uv.y, uv.z, uv.w};
    int   st[4] = {0, 0, 0, 0};   // 0=unclamped, 1=clamped-to-0, 2=clamped-to-upper

    __shared__ float sC, sS, sN;
    __shared__ int   sPhase;
    __shared__ float redA[8], redB[8], redC[8];

    // ---- initial s = sum(y) over the full row ----
    float s0 = yy[0] + yy[1] + yy[2] + yy[3];
    #pragma unroll
    for (int o = 16; o > 0; o >>= 1)
        s0 += __shfl_down_sync(0xffffffffu, s0, o);
    if ((t & 31) == 0) redA[t >> 5] = s0;
    __syncthreads();
    if (t == 0) {
        float s = 0.0f;
        #pragma unroll
        for (int w = 0; w < 8; w++) s += redA[w];
        sS = s; sC = 512.0f; sN = (float)NCOLS; sPhase = 0;
    }
    __syncthreads();

    for (int it = 0; it < 32; ++it) {
        const int phase = sPhase;
        if (phase == 2) break;
        const float fill = (sC - sS) / fmaxf(sN, 1.0f);

        float dn = 0.0f, ds = 0.0f, dc = 0.0f;
        #pragma unroll
        for (int e = 0; e < 4; e++) {
            if (st[e] == 0) {
                const float z = yy[e] + fill;
                const bool viol = (phase == 0) ? (z < 0.0f) : (z > uu[e]);
                if (viol) {
                    st[e] = (phase == 0) ? 1 : 2;
                    dn += 1.0f;
                    ds += yy[e];
                    if (phase == 1) dc += uu[e];
                }
            }
        }
        #pragma unroll
        for (int o = 16; o > 0; o >>= 1) {
            dn += __shfl_down_sync(0xffffffffu, dn, o);
            ds += __shfl_down_sync(0xffffffffu, ds, o);
            dc += __shfl_down_sync(0xffffffffu, dc, o);
        }
        __syncthreads();   // prior-iteration readers of red* are done
        if ((t & 31) == 0) {
            redA[t >> 5] = dn; redB[t >> 5] = ds; redC[t >> 5] = dc;
        }
        __syncthreads();
        if (t == 0) {
            float Dn = 0.0f, Ds = 0.0f, Dc = 0.0f;
            #pragma unroll
            for (int w = 0; w < 8; w++) { Dn += redA[w]; Ds += redB[w]; Dc += redC[w]; }
            if (Dn == 0.0f) sPhase = sPhase + 1;     // no violators -> advance phase
            else { sN -= Dn; sS -= Ds; sC -= Dc; }   // clamp accepted
        }
        __syncthreads();
    }

    // final water level with the final unclamped set (matches reference epilogue)
    const float fill = (sC - sS) / fmaxf(sN, 1.0f);

    float4 ov;
    ov.x = (st[0] == 0) ? yy[0] + fill : ((st[0] == 1) ? 0.0f : uu[0]);
    ov.y = (st[1] == 0) ? yy[1] + fill : ((st[1] == 1) ? 0.0f : uu[1]);
    ov.z = (st[2] == 0) ? yy[2] + fill : ((st[2] == 1) ? 0.0f : uu[2]);
    ov.w = (st[3] == 0) ? yy[3] + fill : ((st[3] == 1) ? 0.0f : uu[3]);
    reinterpret_cast<float4*>(out + (size_t)row * NCOLS)[t] = ov;
}

extern "C" void kernel_launch(void* const* d_in, const int* in_sizes, int n_in,
                              void* d_out, int out_size) {
    const float* y     = (const float*)d_in[0];
    const float* upper = (const float*)d_in[1];
    float*       out   = (float*)d_out;
    const int rows = in_sizes[0] / NCOLS;   // 2048
    proj_kernel<<<rows, THREADS>>>(y, upper, out);
}

// round 2
// speedup vs baseline: 2.0835x; 2.0835x over previous
#include <cuda_runtime.h>

// Batched active-set (water-filling) projection — warp-per-row.
// Each warp owns one row of 1024 elements: 32 elements/lane in registers.
// All reductions are warp-level (shfl_xor butterfly + REDUX count); the row
// state (C, s, n) is replicated in every lane's registers. No shared memory,
// no __syncthreads, independent per-warp early exit.
//
// Phase 0: repeatedly clamp z<0 violators to 0   (dc == 0, skip its reduce)
// Phase 1: repeatedly clamp z>upper violators to upper
// z = y + (C - s)/n over the unclamped set; epilogue matches reference.

#define NCOLS 1024
#define EPL 32              // elements per lane
#define WARPS_PER_BLOCK 4
#define THREADS (WARPS_PER_BLOCK * 32)

__global__ __launch_bounds__(THREADS)
void proj_warp_kernel(const float* __restrict__ y,
                      const float* __restrict__ upper,
                      float* __restrict__ out) {
    const int lane = threadIdx.x & 31;
    const int row  = blockIdx.x * WARPS_PER_BLOCK + (threadIdx.x >> 5);

    const float4* yrow = reinterpret_cast<const float4*>(y + (size_t)row * NCOLS);
    const float4* urow = reinterpret_cast<const float4*>(upper);

    float yv[EPL], uv[EPL];
    #pragma unroll
    for (int k = 0; k < 8; k++) {
        const float4 a = yrow[lane + 32 * k];
        const float4 b = urow[lane + 32 * k];
        yv[4*k+0] = a.x; yv[4*k+1] = a.y; yv[4*k+2] = a.z; yv[4*k+3] = a.w;
        uv[4*k+0] = b.x; uv[4*k+1] = b.y; uv[4*k+2] = b.z; uv[4*k+3] = b.w;
    }

    // initial s = sum(y) over the row
    float s = 0.0f;
    #pragma unroll
    for (int e = 0; e < EPL; e++) s += yv[e];
    #pragma unroll
    for (int o = 16; o; o >>= 1) s += __shfl_xor_sync(0xffffffffu, s, o);

    float    C   = 512.0f;
    int      n   = NCOLS;
    unsigned mUn = 0xffffffffu;   // bit e: element 4-group layout, unclamped
    unsigned mLo = 0u;            // bit e: clamped to lower (0)

    int it = 0;

    // ---- phase 0: clamp z < 0 violators to 0 ----
    while (it < 32) {
        ++it;
        const float fill = (C - s) / fmaxf((float)n, 1.0f);
        unsigned newly = 0u;
        float ds = 0.0f;
        #pragma unroll
        for (int e = 0; e < EPL; e++) {
            if ((mUn >> e) & 1u) {
                const float z = yv[e] + fill;
                if (z < 0.0f) { newly |= (1u << e); ds += yv[e]; }
            }
        }
        const int dn = __reduce_add_sync(0xffffffffu, __popc(newly));
        #pragma unroll
        for (int o = 16; o; o >>= 1) ds += __shfl_xor_sync(0xffffffffu, ds, o);
        if (dn == 0) break;        // phase-advance step (consumes one iteration)
        mUn &= ~newly; mLo |= newly;
        n -= dn; s -= ds;
    }

    // ---- phase 1: clamp z > upper violators to upper ----
    while (it < 32) {
        ++it;
        const float fill = (C - s) / fmaxf((float)n, 1.0f);
        unsigned newly = 0u;
        float ds = 0.0f, dc = 0.0f;
        #pragma unroll
        for (int e = 0; e < EPL; e++) {
            if ((mUn >> e) & 1u) {
                const float z = yv[e] + fill;
                if (z > uv[e]) { newly |= (1u << e); ds += yv[e]; dc += uv[e]; }
            }
        }
        const int dn = __reduce_add_sync(0xffffffffu, __popc(newly));
        #pragma unroll
        for (int o = 16; o; o >>= 1) {
            ds += __shfl_xor_sync(0xffffffffu, ds, o);
            dc += __shfl_xor_sync(0xffffffffu, dc, o);
        }
        if (dn == 0) break;
        mUn &= ~newly;             // upper-clamped: neither mUn nor mLo
        n -= dn; s -= ds; C -= dc;
    }

    // ---- epilogue: final water level over final unclamped set ----
    const float fill = (C - s) / fmaxf((float)n, 1.0f);

    float4* orow = reinterpret_cast<float4*>(out + (size_t)row * NCOLS);
    #pragma unroll
    for (int k = 0; k < 8; k++) {
        float o4[4];
        #pragma unroll
        for (int j = 0; j < 4; j++) {
            const int e = 4 * k + j;
            const bool un = (mUn >> e) & 1u;
            const bool lo = (mLo >> e) & 1u;
            o4[j] = un ? (yv[e] + fill) : (lo ? 0.0f : uv[e]);
        }
        float4 v; v.x = o4[0]; v.y = o4[1]; v.z = o4[2]; v.w = o4[3];
        orow[lane + 32 * k] = v;
    }
}

extern "C" void kernel_launch(void* const* d_in, const int* in_sizes, int n_in,
                              void* d_out, int out_size) {
    const float* y     = (const float*)d_in[0];
    const float* upper = (const float*)d_in[1];
    float*       out   = (float*)d_out;
    const int rows = in_sizes[0] / NCOLS;                 // 2048
    const int blocks = (rows + WARPS_PER_BLOCK - 1) / WARPS_PER_BLOCK;
    proj_warp_kernel<<<blocks, THREADS>>>(y, upper, out);
}

// round 3
// speedup vs baseline: 2.1253x; 1.0201x over previous
#include <cuda_runtime.h>

// Batched active-set (water-filling) projection — warp-per-row, threshold-set
// formulation.
//
// Monotonicity: in phase 0 the water level is non-increasing, so the
// cumulative lower-clamp set is always {e : y[e] < -fill}. In phase 1 it is
// non-decreasing, so the upper-clamp set is {e : y[e]-u[e] > -fill}. Each
// iteration therefore recomputes TOTALS over a pure threshold compare — no
// evolving per-element mask, and phase 1 needs only one float reduction
// (sum of d = y-u over the set). Fill trajectory and iteration accounting
// match the reference's clamp-all-violators rounds exactly.

#define NCOLS 1024
#define EPL 32
#define WARPS_PER_BLOCK 2
#define THREADS (WARPS_PER_BLOCK * 32)

__global__ __launch_bounds__(THREADS)
void proj_kernel(const float* __restrict__ y,
                 const float* __restrict__ upper,
                 float* __restrict__ out) {
    const int lane = threadIdx.x & 31;
    const int row  = blockIdx.x * WARPS_PER_BLOCK + (threadIdx.x >> 5);

    const float4* yrow = reinterpret_cast<const float4*>(y + (size_t)row * NCOLS);
    const float4* urow = reinterpret_cast<const float4*>(upper);

    float yv[EPL], uv[EPL];
    #pragma unroll
    for (int k = 0; k < 8; k++) {
        const float4 a = yrow[lane + 32 * k];
        const float4 b = urow[lane + 32 * k];
        yv[4*k+0] = a.x; yv[4*k+1] = a.y; yv[4*k+2] = a.z; yv[4*k+3] = a.w;
        uv[4*k+0] = b.x; uv[4*k+1] = b.y; uv[4*k+2] = b.z; uv[4*k+3] = b.w;
    }

    // s0 = sum(y) over the row
    float s0 = 0.0f;
    #pragma unroll
    for (int e = 0; e < EPL; e++) s0 += yv[e];
    #pragma unroll
    for (int o = 16; o; o >>= 1) s0 += __shfl_xor_sync(0xffffffffu, s0, o);

    const float C0    = 512.0f;
    const float base0 = C0 - s0;            // fill = (base0 + ds)/(1024 - cnt)
    float fill = base0 * (1.0f / 1024.0f);  // round-1 level (empty clamp set)

    int   it = 0;
    float maskT0;                 // final phase-0 scan threshold (lower mask)
    bool  p0conv = false;
    int   cnt = 0; float ds = 0.0f;

    // ---- phase 0: lower clamps, fill monotone decreasing ----
    {
        int prev = 0;
        for (;;) {
            ++it;
            const float T = -fill;
            int c = 0; float d = 0.0f;
            #pragma unroll
            for (int e = 0; e < EPL; e++) {
                const bool p = yv[e] < T;
                c += p;
                d += p ? yv[e] : 0.0f;
            }
            c = __reduce_add_sync(0xffffffffu, c);
            #pragma unroll
            for (int o = 16; o; o >>= 1) d += __shfl_xor_sync(0xffffffffu, d, o);
            maskT0 = T;
            cnt = c; ds = d;
            if (c == prev) { p0conv = true; break; }   // phase-advance round
            prev = c;
            fill = (base0 + d) / fmaxf((float)(NCOLS - c), 1.0f);
            if (it >= 32) break;                        // budget exhausted
        }
    }

    if (p0conv && it < 32) {
        // ---- phase 1: upper clamps, fill monotone increasing ----
        const float base1 = base0 + ds;           // C0 - s_after_phase0
        const float n1    = (float)(NCOLS - cnt);
        const float NEG_INF = __int_as_float(0xff800000);

        float dd[EPL];
        #pragma unroll
        for (int e = 0; e < EPL; e++)
            dd[e] = (yv[e] < maskT0) ? NEG_INF : (yv[e] - uv[e]);

        float maskT1;
        {
            int prev1 = 0;
            for (;;) {
                ++it;
                const float T = -fill;
                int c = 0; float acc = 0.0f;
                #pragma unroll
                for (int e = 0; e < EPL; e++) {
                    const bool p = dd[e] > T;
                    c += p;
                    acc += p ? dd[e] : 0.0f;
                }
                c = __reduce_add_sync(0xffffffffu, c);
                #pragma unroll
                for (int o = 16; o; o >>= 1) acc += __shfl_xor_sync(0xffffffffu, acc, o);
                maskT1 = T;
                if (c == prev1) break;
                prev1 = c;
                fill = (base1 + acc) / fmaxf(n1 - (float)c, 1.0f);
                if (it >= 32) break;
            }
        }

        // epilogue: lower -> 0, upper -> u (= y - d), else y + fill
        float4* orow = reinterpret_cast<float4*>(out + (size_t)row * NCOLS);
        #pragma unroll
        for (int k = 0; k < 8; k++) {
            float o4[4];
            #pragma unroll
            for (int j = 0; j < 4; j++) {
                const int e = 4 * k + j;
                o4[j] = (yv[e] < maskT0) ? 0.0f
                      : ((dd[e] > maskT1) ? (yv[e] - dd[e]) : (yv[e] + fill));
            }
            float4 v; v.x = o4[0]; v.y = o4[1]; v.z = o4[2]; v.w = o4[3];
            orow[lane + 32 * k] = v;
        }
    } else {
        // phase 1 never ran (budget exhausted in phase 0, or converged at it==32)
        float4* orow = reinterpret_cast<float4*>(out + (size_t)row * NCOLS);
        #pragma unroll
        for (int k = 0; k < 8; k++) {
            float o4[4];
            #pragma unroll
            for (int j = 0; j < 4; j++) {
                const int e = 4 * k + j;
                o4[j] = (yv[e] < maskT0) ? 0.0f : (yv[e] + fill);
            }
            float4 v; v.x = o4[0]; v.y = o4[1]; v.z = o4[2]; v.w = o4[3];
            orow[lane + 32 * k] = v;
        }
    }
}

extern "C" void kernel_launch(void* const* d_in, const int* in_sizes, int n_in,
                              void* d_out, int out_size) {
    const float* y     = (const float*)d_in[0];
    const float* upper = (const float*)d_in[1];
    float*       out   = (float*)d_out;
    const int rows   = in_sizes[0] / NCOLS;                  // 2048
    const int blocks = (rows + WARPS_PER_BLOCK - 1) / WARPS_PER_BLOCK;
    proj_kernel<<<blocks, THREADS>>>(y, upper, out);
}